// round 9
// baseline (speedup 1.0000x reference)
#include <cuda_runtime.h>

#define HH 512
#define WW 512
#define NB 16
#define PLANE (HH*WW)
#define IMG (3*PLANE)
#define R 7
#define K 15
#define TX 128
#define TY 32
#define NTHR 512
#define GX (WW/TX)           // 4
#define GY (HH/TY)           // 16
#define NBLK (GX*GY*NB)      // 1024

#define FRW 164              // luma row stride (mod 32 == 4: anti-conflict pad)
#define FW4 40               // float4 items per row-pair (160 data cols)
#define HRH 30               // row-pair items
#define CRW 82               // chroma row stride (mod 32 == 18)
#define LROWS 70             // dy stored rows 1..60; vy lower -> 0..15, vy upper -> 54..69
#define CROWS 31
#define NITEM (HRH*FW4)      // 1200

// dynamic smem layout (floats)
#define OFF_DU   (LROWS*FRW)
#define OFF_DV   (OFF_DU + CROWS*CRW)
#define OFF_RED  (OFF_DV + CROWS*CRW)
#define SM_FLOATS (OFF_RED + 48)
#define SM_BYTES (SM_FLOATS * 4)

__device__ float g_acc[3];
__device__ unsigned int g_done;

__device__ __forceinline__ float4 f4sub(float4 a, float4 b) {
    return make_float4(a.x-b.x, a.y-b.y, a.z-b.z, a.w-b.w);
}

template<bool SAFE>
__device__ __forceinline__ void phase1(
    const float* __restrict__ pin, const float* __restrict__ ptg,
    float (*s_dy)[FRW], float (*s_du)[CRW], float (*s_dv)[CRW],
    int tx0, int ty0, int tid)
{
    const float4 Z = make_float4(0.f,0.f,0.f,0.f);
    for (int idx = tid; idx < NITEM; idx += NTHR) {
        int hr  = idx / FW4;
        int hc2 = idx - hr * FW4;
        int fy = ty0 - 2*R + 2*hr;        // even
        int fx = tx0 - 16 + 4*hc2;        // multiple of 4 -> 16B aligned

        int o0 = fy * WW + fx;
        int o1 = o0 + WW;

        bool p0 = true, p1 = true;
        if (!SAFE) {
            bool cx = (fx >= 0) & (fx < WW);
            p0 = cx & (fy >= 0)     & (fy < HH);
            p1 = cx & (fy + 1 >= 0) & (fy + 1 < HH);
        }

        // channel R
        float4 a0 = (SAFE || p0) ? *(const float4*)(pin + o0) : Z;
        float4 a1 = (SAFE || p1) ? *(const float4*)(pin + o1) : Z;
        float4 b0 = (SAFE || p0) ? *(const float4*)(ptg + o0) : Z;
        float4 b1 = (SAFE || p1) ? *(const float4*)(ptg + o1) : Z;
        float4 dr0 = f4sub(a0, b0), dr1 = f4sub(a1, b1);
        // channel G
        a0 = (SAFE || p0) ? *(const float4*)(pin + PLANE + o0) : Z;
        a1 = (SAFE || p1) ? *(const float4*)(pin + PLANE + o1) : Z;
        b0 = (SAFE || p0) ? *(const float4*)(ptg + PLANE + o0) : Z;
        b1 = (SAFE || p1) ? *(const float4*)(ptg + PLANE + o1) : Z;
        float4 dg0 = f4sub(a0, b0), dg1 = f4sub(a1, b1);
        // channel B
        a0 = (SAFE || p0) ? *(const float4*)(pin + 2*PLANE + o0) : Z;
        a1 = (SAFE || p1) ? *(const float4*)(pin + 2*PLANE + o1) : Z;
        b0 = (SAFE || p0) ? *(const float4*)(ptg + 2*PLANE + o0) : Z;
        b1 = (SAFE || p1) ? *(const float4*)(ptg + 2*PLANE + o1) : Z;
        float4 db0 = f4sub(a0, b0), db1 = f4sub(a1, b1);

        // luma diffs (8 pixels)
        float4 y0 = make_float4(
            0.299f*dr0.x + 0.587f*dg0.x + 0.114f*db0.x,
            0.299f*dr0.y + 0.587f*dg0.y + 0.114f*db0.y,
            0.299f*dr0.z + 0.587f*dg0.z + 0.114f*db0.z,
            0.299f*dr0.w + 0.587f*dg0.w + 0.114f*db0.w);
        float4 y1 = make_float4(
            0.299f*dr1.x + 0.587f*dg1.x + 0.114f*db1.x,
            0.299f*dr1.y + 0.587f*dg1.y + 0.114f*db1.y,
            0.299f*dr1.z + 0.587f*dg1.z + 0.114f*db1.z,
            0.299f*dr1.w + 0.587f*dg1.w + 0.114f*db1.w);

        // pooled 2x2 chroma diffs (+128 offsets cancel)
        float DrA = dr0.x + dr0.y + dr1.x + dr1.y;
        float DrB = dr0.z + dr0.w + dr1.z + dr1.w;
        float DgA = dg0.x + dg0.y + dg1.x + dg1.y;
        float DgB = dg0.z + dg0.w + dg1.z + dg1.w;
        float DbA = db0.x + db0.y + db1.x + db1.y;
        float DbB = db0.z + db0.w + db1.z + db1.w;

        float2 du = make_float2(
            0.25f * (-0.169f*DrA - 0.331f*DgA + 0.5f *DbA),
            0.25f * (-0.169f*DrB - 0.331f*DgB + 0.5f *DbB));
        float2 dv = make_float2(
            0.25f * ( 0.5f  *DrA - 0.46f *DgA - 0.04f*DbA),
            0.25f * ( 0.5f  *DrB - 0.46f *DgB - 0.04f*DbB));

        int lr0 = 2*hr + 1;               // stored luma rows 1..60
        *(float4*)&s_dy[lr0][4*hc2]     = y0;
        *(float4*)&s_dy[lr0 + 1][4*hc2] = y1;
        *(float2*)&s_du[hr + 1][2*hc2] = du;
        *(float2*)&s_dv[hr + 1][2*hc2] = dv;
    }
}

__global__ __launch_bounds__(NTHR, 3) void yuv_loss_kernel(
    const float* __restrict__ inp, const float* __restrict__ tgt,
    float* __restrict__ out)
{
    extern __shared__ float sm[];
    float (*s_dy)[FRW] = (float (*)[FRW])(sm);
    float (*s_du)[CRW] = (float (*)[CRW])(sm + OFF_DU);
    float (*s_dv)[CRW] = (float (*)[CRW])(sm + OFF_DV);
    float* s_red = sm + OFF_RED;

    const int tid = threadIdx.x;
    const int n   = blockIdx.z;
    const int tx0 = blockIdx.x * TX;
    const int ty0 = blockIdx.y * TY;
    const float* pin = inp + (size_t)n * IMG;
    const float* ptg = tgt + (size_t)n * IMG;

    // ---- Phase 1 ----
    bool interior = (tx0 >= 16) & (tx0 + TX + 16 <= WW) &
                    (ty0 >= 2*R) & (ty0 + TY + 2*R + 2 <= HH);
    if (interior) phase1<true >(pin, ptg, s_dy, s_du, s_dv, tx0, ty0, tid);
    else          phase1<false>(pin, ptg, s_dy, s_du, s_dv, tx0, ty0, tid);
    __syncthreads();

    // ---- Phase 2: vertical 15-tap running sums ----
    // dy region row i lives at stored row i+1 (region row 0 = full-res ty0-14).
    // vy[r] (output row r) = sum of stored rows r+8 .. r+22.
    // Lower half (r=0..15): write in place to stored row r
    //   (row x in [8,15] is read at step x-7 BEFORE being written at step x; columns
    //    are thread-private so ordering is per-thread sequential -> safe).
    // Upper half (r=16..31): reads stored rows 24..53, writes spare rows 54..69
    //   (disjoint from all reads of both halves -> no cross-warp race).
    if (tid < 284) {
        int c = (tid < 142 ? tid : tid - 142) + 9;
        if (tid < 142) {                 // vy rows 0..15
            float s = 0.f;
            #pragma unroll
            for (int j = 8; j <= 22; j++) s += s_dy[j][c];
            s_dy[0][c] = s;
            #pragma unroll 4
            for (int r = 1; r < 16; r++) {
                s += s_dy[r + 22][c] - s_dy[r + 7][c];
                s_dy[r][c] = s;
            }
        } else {                         // vy rows 16..31 -> stored rows 54..69
            float s = 0.f;
            #pragma unroll
            for (int j = 24; j <= 38; j++) s += s_dy[j][c];
            s_dy[54][c] = s;
            #pragma unroll 4
            for (int r = 17; r < 32; r++) {
                s += s_dy[r + 22][c] - s_dy[r + 7][c];
                s_dy[r + 38][c] = s;
            }
        }
    } else if (tid < 284 + 156) {        // chroma: 2 ch x 78 cols (cols 1..78)
        int t = tid - 284;
        int ch = (t >= 78);
        int c  = (ch ? t - 78 : t) + 1;
        float (*b)[CRW] = ch ? s_dv : s_du;
        float s = 0.f;
        #pragma unroll
        for (int j = 1; j <= 15; j++) s += b[j][c];
        b[0][c] = s;
        #pragma unroll 5
        for (int r = 1; r < 16; r++) {
            s += b[r + 15][c] - b[r][c];
            b[r][c] = s;
        }
    }
    __syncthreads();

    // ---- Phase 3: horizontal 15-tap sliding sums, square, accumulate ----
    float accY = 0.f, accU = 0.f, accV = 0.f;
    {   // luma: 32 rows x 16 segments of 8 outputs
        int row = tid >> 4;
        int srow = (row < 16) ? row : row + 38;
        int c0  = (tid & 15) * 8 + 9;       // output x reads vy cols x+9..x+23
        float s = 0.f;
        #pragma unroll
        for (int j = 0; j < K; j++) s += s_dy[srow][c0 + j];
        accY = s * s;
        #pragma unroll
        for (int i = 1; i < 8; i++) {
            s += s_dy[srow][c0 + i + K - 1] - s_dy[srow][c0 + i - 1];
            accY += s * s;
        }
    }
    {   // chroma: 2 ch x 16 rows x 16 segments of 4 outputs
        int ch  = tid >> 8;
        int rem = tid & 255;
        int row = rem >> 4;
        int c0  = (rem & 15) * 4 + 1;
        float (*v)[CRW] = ch ? s_dv : s_du;
        float s = 0.f;
        #pragma unroll
        for (int j = 0; j < K; j++) s += v[row][c0 + j];
        float a = s * s;
        #pragma unroll
        for (int i = 1; i < 4; i++) {
            s += v[row][c0 + i + K - 1] - v[row][c0 + i - 1];
            a += s * s;
        }
        if (ch) accV = a; else accU = a;
    }

    // ---- block reduction (16 warps) ----
    #pragma unroll
    for (int o = 16; o > 0; o >>= 1) {
        accY += __shfl_down_sync(0xffffffffu, accY, o);
        accU += __shfl_down_sync(0xffffffffu, accU, o);
        accV += __shfl_down_sync(0xffffffffu, accV, o);
    }
    int w = tid >> 5, l = tid & 31;
    if (l == 0) { s_red[w] = accY; s_red[16 + w] = accU; s_red[32 + w] = accV; }
    __syncthreads();
    if (tid == 0) {
        float sy = 0.f, su = 0.f, sv = 0.f;
        #pragma unroll
        for (int i = 0; i < 16; i++) { sy += s_red[i]; su += s_red[16+i]; sv += s_red[32+i]; }
        atomicAdd(&g_acc[0], sy);
        atomicAdd(&g_acc[1], su);
        atomicAdd(&g_acc[2], sv);
        __threadfence();
        unsigned int t = atomicAdd(&g_done, 1u);
        if (t == NBLK - 1) {
            const float invY = 1.0f / ((float)NB * HH * WW);
            const float invC = 1.0f / ((float)NB * (HH/2) * (WW/2));
            out[0] = g_acc[0] * invY + (g_acc[1] + g_acc[2]) * invC;
            g_acc[0] = 0.f; g_acc[1] = 0.f; g_acc[2] = 0.f;
            g_done = 0u;
        }
    }
}

extern "C" void kernel_launch(void* const* d_in, const int* in_sizes, int n_in,
                              void* d_out, int out_size)
{
    const float* inp = (const float*)d_in[0];
    const float* tgt = (const float*)d_in[1];
    float* out = (float*)d_out;

    static int configured = 0;
    if (!configured) {
        cudaFuncSetAttribute(yuv_loss_kernel,
                             cudaFuncAttributeMaxDynamicSharedMemorySize, SM_BYTES);
        configured = 1;
    }

    dim3 grid(GX, GY, NB);
    yuv_loss_kernel<<<grid, NTHR, SM_BYTES>>>(inp, tgt, out);
}

// round 10
// speedup vs baseline: 1.4325x; 1.4325x over previous
#include <cuda_runtime.h>

#define HH 512
#define WW 512
#define NB 16
#define PLANE (HH*WW)
#define IMG (3*PLANE)
#define R 7
#define K 15
#define TX 128
#define TY 32
#define NTHR 512
#define GX (WW/TX)           // 4
#define GY (HH/TY)           // 16
#define NBLK (GX*GY*NB)      // 1024

#define FRW 164              // luma row stride (mod 32 == 4: anti-conflict pad)
#define FW4 40               // float4 items per row-pair (160 data cols)
#define HRH 30               // row-pair items
#define CRW 82               // chroma row stride (mod 32 == 18)
#define LROWS 54             // stored dy rows 1..53 used; vy rows 0..31 in place
#define CROWS 31
#define NITEM (HRH*FW4)      // 1200

// dynamic smem layout (floats)
#define OFF_DU   (LROWS*FRW)
#define OFF_DV   (OFF_DU + CROWS*CRW)
#define OFF_RED  (OFF_DV + CROWS*CRW)
#define SM_FLOATS (OFF_RED + 48)
#define SM_BYTES (SM_FLOATS * 4)

__device__ float g_acc[3];
__device__ unsigned int g_done;

__device__ __forceinline__ float4 f4sub(float4 a, float4 b) {
    return make_float4(a.x-b.x, a.y-b.y, a.z-b.z, a.w-b.w);
}

template<bool SAFE>
__device__ __forceinline__ void phase1(
    const float* __restrict__ pin, const float* __restrict__ ptg,
    float (*s_dy)[FRW], float (*s_du)[CRW], float (*s_dv)[CRW],
    int tx0, int ty0, int tid)
{
    const float4 Z = make_float4(0.f,0.f,0.f,0.f);
    for (int idx = tid; idx < NITEM; idx += NTHR) {
        int hr  = idx / FW4;
        int hc2 = idx - hr * FW4;
        int fy = ty0 - 2*R + 2*hr;        // even
        int fx = tx0 - 16 + 4*hc2;        // multiple of 4 -> 16B aligned

        int o0 = fy * WW + fx;
        int o1 = o0 + WW;

        bool p0 = true, p1 = true;
        if (!SAFE) {
            bool cx = (fx >= 0) & (fx < WW);
            p0 = cx & (fy >= 0)     & (fy < HH);
            p1 = cx & (fy + 1 >= 0) & (fy + 1 < HH);
        }

        // channel R
        float4 a0 = (SAFE || p0) ? *(const float4*)(pin + o0) : Z;
        float4 a1 = (SAFE || p1) ? *(const float4*)(pin + o1) : Z;
        float4 b0 = (SAFE || p0) ? *(const float4*)(ptg + o0) : Z;
        float4 b1 = (SAFE || p1) ? *(const float4*)(ptg + o1) : Z;
        float4 dr0 = f4sub(a0, b0), dr1 = f4sub(a1, b1);
        // channel G
        a0 = (SAFE || p0) ? *(const float4*)(pin + PLANE + o0) : Z;
        a1 = (SAFE || p1) ? *(const float4*)(pin + PLANE + o1) : Z;
        b0 = (SAFE || p0) ? *(const float4*)(ptg + PLANE + o0) : Z;
        b1 = (SAFE || p1) ? *(const float4*)(ptg + PLANE + o1) : Z;
        float4 dg0 = f4sub(a0, b0), dg1 = f4sub(a1, b1);
        // channel B
        a0 = (SAFE || p0) ? *(const float4*)(pin + 2*PLANE + o0) : Z;
        a1 = (SAFE || p1) ? *(const float4*)(pin + 2*PLANE + o1) : Z;
        b0 = (SAFE || p0) ? *(const float4*)(ptg + 2*PLANE + o0) : Z;
        b1 = (SAFE || p1) ? *(const float4*)(ptg + 2*PLANE + o1) : Z;
        float4 db0 = f4sub(a0, b0), db1 = f4sub(a1, b1);

        // luma diffs (8 pixels)
        float4 y0 = make_float4(
            0.299f*dr0.x + 0.587f*dg0.x + 0.114f*db0.x,
            0.299f*dr0.y + 0.587f*dg0.y + 0.114f*db0.y,
            0.299f*dr0.z + 0.587f*dg0.z + 0.114f*db0.z,
            0.299f*dr0.w + 0.587f*dg0.w + 0.114f*db0.w);
        float4 y1 = make_float4(
            0.299f*dr1.x + 0.587f*dg1.x + 0.114f*db1.x,
            0.299f*dr1.y + 0.587f*dg1.y + 0.114f*db1.y,
            0.299f*dr1.z + 0.587f*dg1.z + 0.114f*db1.z,
            0.299f*dr1.w + 0.587f*dg1.w + 0.114f*db1.w);

        // pooled 2x2 chroma diffs (+128 offsets cancel)
        float DrA = dr0.x + dr0.y + dr1.x + dr1.y;
        float DrB = dr0.z + dr0.w + dr1.z + dr1.w;
        float DgA = dg0.x + dg0.y + dg1.x + dg1.y;
        float DgB = dg0.z + dg0.w + dg1.z + dg1.w;
        float DbA = db0.x + db0.y + db1.x + db1.y;
        float DbB = db0.z + db0.w + db1.z + db1.w;

        float2 du = make_float2(
            0.25f * (-0.169f*DrA - 0.331f*DgA + 0.5f *DbA),
            0.25f * (-0.169f*DrB - 0.331f*DgB + 0.5f *DbB));
        float2 dv = make_float2(
            0.25f * ( 0.5f  *DrA - 0.46f *DgA - 0.04f*DbA),
            0.25f * ( 0.5f  *DrB - 0.46f *DgB - 0.04f*DbB));

        // stores: luma rows stored at region_row+1, keep rows <= 53
        int lr0 = 2*hr + 1;
        if (lr0 <= LROWS - 1)     *(float4*)&s_dy[lr0][4*hc2]     = y0;
        if (lr0 + 1 <= LROWS - 1) *(float4*)&s_dy[lr0 + 1][4*hc2] = y1;
        *(float2*)&s_du[hr + 1][2*hc2] = du;
        *(float2*)&s_dv[hr + 1][2*hc2] = dv;
    }
}

__global__ __launch_bounds__(NTHR, 3) void yuv_loss_kernel(
    const float* __restrict__ inp, const float* __restrict__ tgt,
    float* __restrict__ out)
{
    extern __shared__ float sm[];
    float (*s_dy)[FRW] = (float (*)[FRW])(sm);
    float (*s_du)[CRW] = (float (*)[CRW])(sm + OFF_DU);
    float (*s_dv)[CRW] = (float (*)[CRW])(sm + OFF_DV);
    float* s_red = sm + OFF_RED;

    const int tid = threadIdx.x;
    const int n   = blockIdx.z;
    const int tx0 = blockIdx.x * TX;
    const int ty0 = blockIdx.y * TY;
    const float* pin = inp + (size_t)n * IMG;
    const float* ptg = tgt + (size_t)n * IMG;

    // ---- Phase 1 ----
    bool interior = (tx0 >= 16) & (tx0 + TX + 16 <= WW) &
                    (ty0 >= 2*R) & (ty0 + TY + 2*R + 2 <= HH);
    if (interior) phase1<true >(pin, ptg, s_dy, s_du, s_dv, tx0, ty0, tid);
    else          phase1<false>(pin, ptg, s_dy, s_du, s_dv, tx0, ty0, tid);
    __syncthreads();

    // ---- Phase 2: vertical 15-tap running sums, in place (R6-verified windows) ----
    // dy region row i at stored row i+1; vy[r] = sum(stored r+8 .. r+22) -> stored row r.
    // Per-thread sequential: stored row x is read at steps x-22 (+) and x-7 (-),
    // both BEFORE its overwrite at step x -> safe.
    if (tid < 142) {
        int c = tid + 9;
        float s = 0.f;
        #pragma unroll
        for (int j = 8; j <= 22; j++) s += s_dy[j][c];
        s_dy[0][c] = s;
        #pragma unroll 4
        for (int r = 1; r < TY; r++) {
            s += s_dy[r + 22][c] - s_dy[r + 7][c];
            s_dy[r][c] = s;
        }
    } else if (tid < 142 + 156) {     // chroma: 2 ch x 78 cols (cols 1..78)
        int t = tid - 142;
        int ch = (t >= 78);
        int c  = (ch ? t - 78 : t) + 1;
        float (*b)[CRW] = ch ? s_dv : s_du;
        float s = 0.f;
        #pragma unroll
        for (int j = 1; j <= 15; j++) s += b[j][c];
        b[0][c] = s;
        #pragma unroll 5
        for (int r = 1; r < TY/2; r++) {
            s += b[r + 15][c] - b[r][c];
            b[r][c] = s;
        }
    }
    __syncthreads();

    // ---- Phase 3: horizontal 15-tap sliding sums, square, accumulate ----
    float accY = 0.f, accU = 0.f, accV = 0.f;
    {   // luma: 32 rows x 16 segments of 8 outputs
        int row = tid >> 4;
        int c0  = (tid & 15) * 8 + 9;       // output x reads vy cols x+9..x+23
        float s = 0.f;
        #pragma unroll
        for (int j = 0; j < K; j++) s += s_dy[row][c0 + j];
        accY = s * s;
        #pragma unroll
        for (int i = 1; i < 8; i++) {
            s += s_dy[row][c0 + i + K - 1] - s_dy[row][c0 + i - 1];
            accY += s * s;
        }
    }
    {   // chroma: 2 ch x 16 rows x 16 segments of 4 outputs
        int ch  = tid >> 8;
        int rem = tid & 255;
        int row = rem >> 4;
        int c0  = (rem & 15) * 4 + 1;
        float (*v)[CRW] = ch ? s_dv : s_du;
        float s = 0.f;
        #pragma unroll
        for (int j = 0; j < K; j++) s += v[row][c0 + j];
        float a = s * s;
        #pragma unroll
        for (int i = 1; i < 4; i++) {
            s += v[row][c0 + i + K - 1] - v[row][c0 + i - 1];
            a += s * s;
        }
        if (ch) accV = a; else accU = a;
    }

    // ---- block reduction (16 warps) ----
    #pragma unroll
    for (int o = 16; o > 0; o >>= 1) {
        accY += __shfl_down_sync(0xffffffffu, accY, o);
        accU += __shfl_down_sync(0xffffffffu, accU, o);
        accV += __shfl_down_sync(0xffffffffu, accV, o);
    }
    int w = tid >> 5, l = tid & 31;
    if (l == 0) { s_red[w] = accY; s_red[16 + w] = accU; s_red[32 + w] = accV; }
    __syncthreads();
    if (tid == 0) {
        float sy = 0.f, su = 0.f, sv = 0.f;
        #pragma unroll
        for (int i = 0; i < 16; i++) { sy += s_red[i]; su += s_red[16+i]; sv += s_red[32+i]; }
        atomicAdd(&g_acc[0], sy);
        atomicAdd(&g_acc[1], su);
        atomicAdd(&g_acc[2], sv);
        __threadfence();
        unsigned int t = atomicAdd(&g_done, 1u);
        if (t == NBLK - 1) {
            const float invY = 1.0f / ((float)NB * HH * WW);
            const float invC = 1.0f / ((float)NB * (HH/2) * (WW/2));
            out[0] = g_acc[0] * invY + (g_acc[1] + g_acc[2]) * invC;
            g_acc[0] = 0.f; g_acc[1] = 0.f; g_acc[2] = 0.f;
            g_done = 0u;
        }
    }
}

extern "C" void kernel_launch(void* const* d_in, const int* in_sizes, int n_in,
                              void* d_out, int out_size)
{
    const float* inp = (const float*)d_in[0];
    const float* tgt = (const float*)d_in[1];
    float* out = (float*)d_out;

    static int configured = 0;
    if (!configured) {
        cudaFuncSetAttribute(yuv_loss_kernel,
                             cudaFuncAttributeMaxDynamicSharedMemorySize, SM_BYTES);
        configured = 1;
    }

    dim3 grid(GX, GY, NB);
    yuv_loss_kernel<<<grid, NTHR, SM_BYTES>>>(inp, tgt, out);
}